// round 6
// baseline (speedup 1.0000x reference)
#include <cuda_runtime.h>
#include <cuda_bf16.h>
#include <cstdint>

#define BQ 4096
#define NTOK 49
#define EMB 256
#define NHEADS 8
#define HD 32
#define MROWS (BQ*NTOK)   // 200704 = 128*1568
#define SPAD 40           // bf16 row stride (32 data + 8 pad): conflict-free ldmatrix

// Scratch (device globals: allocation-free), 16B aligned for float4 access
__device__ __align__(16) float g_q[BQ*NHEADS*NTOK*HD];
__device__ __align__(16) float g_k[BQ*NHEADS*NTOK*HD];
__device__ __align__(16) float g_v[BQ*NHEADS*NTOK*HD];
__device__ __align__(16) float g_att[MROWS*EMB];
__device__ __align__(16) float g_cmb[64*NHEADS*NTOK*64];  // mask+bias, j padded to 64

// ---------------------------------------------------------------------------
// PTX helpers
// ---------------------------------------------------------------------------
__device__ __forceinline__ uint32_t smem_u32(const void* p) {
    uint32_t a;
    asm("{ .reg .u64 t; cvta.to.shared.u64 t, %1; cvt.u32.u64 %0, t; }"
        : "=r"(a) : "l"(p));
    return a;
}

__device__ __forceinline__ void ldm_x4(uint32_t& r0, uint32_t& r1,
                                       uint32_t& r2, uint32_t& r3, uint32_t addr) {
    asm volatile("ldmatrix.sync.aligned.m8n8.x4.shared.b16 {%0,%1,%2,%3}, [%4];"
                 : "=r"(r0), "=r"(r1), "=r"(r2), "=r"(r3) : "r"(addr));
}

__device__ __forceinline__ void mma_bf16(float* c, uint32_t a0, uint32_t a1,
                                         uint32_t a2, uint32_t a3,
                                         uint32_t b0, uint32_t b1) {
    asm volatile(
        "mma.sync.aligned.m16n8k16.row.col.f32.bf16.bf16.f32 "
        "{%0,%1,%2,%3}, {%4,%5,%6,%7}, {%8,%9}, {%0,%1,%2,%3};"
        : "+f"(c[0]), "+f"(c[1]), "+f"(c[2]), "+f"(c[3])
        : "r"(a0), "r"(a1), "r"(a2), "r"(a3), "r"(b0), "r"(b1));
}

__device__ __forceinline__ uint32_t pack_bf2(float a, float b) {
    __nv_bfloat162 v = __floats2bfloat162_rn(a, b);
    return *reinterpret_cast<uint32_t*>(&v);
}

// packed f32x2 (Blackwell; PTX-only path, see SASS_QUICKREF FFMA2)
__device__ __forceinline__ unsigned long long pk2(float x, float y) {
    unsigned long long r;
    asm("mov.b64 %0, {%1, %2};" : "=l"(r) : "f"(x), "f"(y));
    return r;
}
__device__ __forceinline__ float2 upk2(unsigned long long v) {
    float2 f;
    asm("mov.b64 {%0, %1}, %2;" : "=f"(f.x), "=f"(f.y) : "l"(v));
    return f;
}
__device__ __forceinline__ void fma2(unsigned long long& d,
                                     unsigned long long a, unsigned long long b) {
    asm("fma.rn.f32x2 %0, %1, %2, %0;" : "+l"(d) : "l"(a), "l"(b));
}

// ---------------------------------------------------------------------------
// split 16 fp32 -> bf16 hi/lo, store to smem (16B stores; ptrs 16B aligned)
// ---------------------------------------------------------------------------
__device__ __forceinline__ void split16(const float* __restrict__ g,
                                        __nv_bfloat16* sh, __nv_bfloat16* sl) {
    float4 v0 = ((const float4*)g)[0];
    float4 v1 = ((const float4*)g)[1];
    float4 v2 = ((const float4*)g)[2];
    float4 v3 = ((const float4*)g)[3];
    const float f[16] = {v0.x,v0.y,v0.z,v0.w, v1.x,v1.y,v1.z,v1.w,
                         v2.x,v2.y,v2.z,v2.w, v3.x,v3.y,v3.z,v3.w};
    uint32_t h[8], l[8];
#pragma unroll
    for (int e = 0; e < 8; ++e) {
        const float x0 = f[2*e], x1 = f[2*e+1];
        h[e] = pack_bf2(x0, x1);
        const __nv_bfloat162 hv = *reinterpret_cast<const __nv_bfloat162*>(&h[e]);
        l[e] = pack_bf2(x0 - __bfloat162float(hv.x), x1 - __bfloat162float(hv.y));
    }
    ((uint4*)sh)[0] = make_uint4(h[0],h[1],h[2],h[3]);
    ((uint4*)sh)[1] = make_uint4(h[4],h[5],h[6],h[7]);
    ((uint4*)sl)[0] = make_uint4(l[0],l[1],l[2],l[3]);
    ((uint4*)sl)[1] = make_uint4(l[4],l[5],l[6],l[7]);
}

// ---------------------------------------------------------------------------
// HMMA GEMM: 128x128 CTA tile, 4 warps (64x64 warp tiles -> ldmatrix:mma 1:6),
// K in 8 chunks of 32, bf16 hi/lo split (3 passes). 2 CTAs/SM.
// MODE 0: A=x, W=qkv_w, scatter q/k/v (q scaled).  MODE 1: A=g_att, W=proj_w.
// ---------------------------------------------------------------------------
template<int MODE>
__global__ void __launch_bounds__(128, 2)
gemm_hmma(const float* __restrict__ A_in, const float* __restrict__ W,
          const float* __restrict__ bias, float* __restrict__ out)
{
    __shared__ __align__(16) __nv_bfloat16 s_ahi[128 * SPAD];
    __shared__ __align__(16) __nv_bfloat16 s_alo[128 * SPAD];
    __shared__ __align__(16) __nv_bfloat16 s_bhi[128 * SPAD];
    __shared__ __align__(16) __nv_bfloat16 s_blo[128 * SPAD];

    const float* __restrict__ A = (MODE == 0) ? A_in : (const float*)g_att;

    const int tid = threadIdx.x;
    const int wid = tid >> 5;
    const int lid = tid & 31;
    const int m0  = blockIdx.y * 128;
    const int n0b = blockIdx.x * 128;
    const int warpM = (wid >> 1) * 64;
    const int warpN = (wid & 1) * 64;

    const uint32_t uAhi = smem_u32(s_ahi);
    const uint32_t uAlo = smem_u32(s_alo);
    const uint32_t uBhi = smem_u32(s_bhi);
    const uint32_t uBlo = smem_u32(s_blo);

    // each thread owns one full row (32 k) of A and of B per chunk
    const float* Ag = A + (m0  + tid) * EMB;
    const float* Wg = W + (n0b + tid) * EMB;
    __nv_bfloat16* sa_h = s_ahi + tid * SPAD;
    __nv_bfloat16* sa_l = s_alo + tid * SPAD;
    __nv_bfloat16* sb_h = s_bhi + tid * SPAD;
    __nv_bfloat16* sb_l = s_blo + tid * SPAD;

    float acc[4][8][4];
#pragma unroll
    for (int i = 0; i < 4; i++)
#pragma unroll
        for (int j = 0; j < 8; j++)
#pragma unroll
            for (int r = 0; r < 4; r++) acc[i][j][r] = 0.f;

    const int aRow = warpM + (lid & 15);
    const int aCol = (lid >> 4) << 3;
    const int bRow = warpN + ((lid >> 4) << 3) + (lid & 7);
    const int bCol = ((lid >> 3) & 1) << 3;

    for (int c = 0; c < 8; ++c) {
        __syncthreads();   // protect smem from previous iteration's ldmatrix
        split16(Ag + c*32,      sa_h,      sa_l);
        split16(Ag + c*32 + 16, sa_h + 16, sa_l + 16);
        split16(Wg + c*32,      sb_h,      sb_l);
        split16(Wg + c*32 + 16, sb_h + 16, sb_l + 16);
        __syncthreads();

#pragma unroll
        for (int kk = 0; kk < 32; kk += 16) {
            uint32_t a[4][4], bh[8][2], bl[8][2];
#pragma unroll
            for (int i = 0; i < 4; ++i) {
                const uint32_t off = (uint32_t)(((aRow + i*16) * SPAD + kk + aCol) * 2);
                ldm_x4(a[i][0], a[i][1], a[i][2], a[i][3], uAhi + off);
            }
#pragma unroll
            for (int jj = 0; jj < 4; ++jj) {
                const uint32_t off = (uint32_t)(((bRow + jj*16) * SPAD + kk + bCol) * 2);
                uint32_t r0, r1, r2, r3;
                ldm_x4(r0, r1, r2, r3, uBhi + off);
                bh[jj*2+0][0] = r0; bh[jj*2+0][1] = r1;
                bh[jj*2+1][0] = r2; bh[jj*2+1][1] = r3;
            }
            // pass 1: Ah * Bh
#pragma unroll
            for (int i = 0; i < 4; ++i)
#pragma unroll
                for (int j = 0; j < 8; ++j)
                    mma_bf16(acc[i][j], a[i][0],a[i][1],a[i][2],a[i][3],
                             bh[j][0], bh[j][1]);
            // pass 2: Ah * Bl
#pragma unroll
            for (int jj = 0; jj < 4; ++jj) {
                const uint32_t off = (uint32_t)(((bRow + jj*16) * SPAD + kk + bCol) * 2);
                uint32_t r0, r1, r2, r3;
                ldm_x4(r0, r1, r2, r3, uBlo + off);
                bl[jj*2+0][0] = r0; bl[jj*2+0][1] = r1;
                bl[jj*2+1][0] = r2; bl[jj*2+1][1] = r3;
            }
#pragma unroll
            for (int i = 0; i < 4; ++i)
#pragma unroll
                for (int j = 0; j < 8; ++j)
                    mma_bf16(acc[i][j], a[i][0],a[i][1],a[i][2],a[i][3],
                             bl[j][0], bl[j][1]);
            // pass 3: Al * Bh (reuse a regs)
#pragma unroll
            for (int i = 0; i < 4; ++i) {
                const uint32_t off = (uint32_t)(((aRow + i*16) * SPAD + kk + aCol) * 2);
                ldm_x4(a[i][0], a[i][1], a[i][2], a[i][3], uAlo + off);
            }
#pragma unroll
            for (int i = 0; i < 4; ++i)
#pragma unroll
                for (int j = 0; j < 8; ++j)
                    mma_bf16(acc[i][j], a[i][0],a[i][1],a[i][2],a[i][3],
                             bh[j][0], bh[j][1]);
        }
    }

    // ---- epilogue ----
#pragma unroll
    for (int i = 0; i < 4; ++i) {
#pragma unroll
        for (int j = 0; j < 8; ++j) {
            const int n = n0b + warpN + j * 8 + 2 * (lid & 3);
            const float b0 = bias[n], b1 = bias[n + 1];
#pragma unroll
            for (int half = 0; half < 2; ++half) {
                const int m = m0 + warpM + i * 16 + (lid >> 2) + half * 8;
                float2 o;
                o.x = acc[i][j][half*2+0] + b0;
                o.y = acc[i][j][half*2+1] + b1;
                if (MODE == 0) {
                    const int bb  = m / NTOK;
                    const int nn  = m - bb * NTOK;
                    const int sel = n >> 8;
                    const int h   = (n >> 5) & 7;
                    const int d   = n & 31;
                    if (sel == 0) { o.x *= 0.17677669529663687f; o.y *= 0.17677669529663687f; }
                    float* dst = (sel == 0 ? g_q : (sel == 1 ? g_k : g_v))
                                 + ((bb * NHEADS + h) * NTOK + nn) * HD + d;
                    *(float2*)dst = o;
                } else {
                    *(float2*)(out + m * EMB + n) = o;
                }
            }
        }
    }
}

// ---------------------------------------------------------------------------
// Precompute combined mask + relative-position bias: [64*8][49][64] (j padded)
// ---------------------------------------------------------------------------
__global__ void __launch_bounds__(256)
cmb_kernel(const float* __restrict__ mask, const float* __restrict__ bias_table)
{
    const int wh = blockIdx.x;           // 0..511 = w*8 + h
    const int w  = wh >> 3;
    const int h  = wh & 7;
    for (int e = threadIdx.x; e < NTOK * 64; e += 256) {
        const int q = e >> 6;
        const int j = e & 63;
        float v = 0.f;
        if (j < NTOK) {
            const int qi = q / 7, qj = q - (q / 7) * 7;
            const int ki = j / 7, kj = j - (j / 7) * 7;
            const int idx = (qi - ki + 6) * 13 + (qj - kj + 6);
            v = mask[(w * NTOK + q) * NTOK + j] + bias_table[idx * NHEADS + h];
        }
        g_cmb[(wh * NTOK + q) * 64 + j] = v;
    }
}

// ---------------------------------------------------------------------------
// Attention: one block per (b,h). Logits fully in registers (p[49]); combined
// mask+bias preloaded as logit init; f32x2 packed FMAs in QK and PV loops.
// ---------------------------------------------------------------------------
__global__ void __launch_bounds__(64)
attn_kernel()
{
    __shared__ __align__(16) float sk[NTOK * 32];
    __shared__ __align__(16) float sv[NTOK * 32];

    const int tid = threadIdx.x;
    const int bh  = blockIdx.x;
    const int b   = bh >> 3;
    const int h   = bh & 7;

    const float* kp = g_k + bh * (NTOK * HD);
    const float* vp = g_v + bh * (NTOK * HD);
    for (int i = tid; i < (NTOK * HD) / 4; i += 64) {
        ((float4*)sk)[i] = ((const float4*)kp)[i];
        ((float4*)sv)[i] = ((const float4*)vp)[i];
    }
    __syncthreads();

    if (tid < NTOK) {
        // logits init = combined mask + bias row
        float p[NTOK];
        const float* crow = g_cmb + ((((b & 63) * NHEADS + h) * NTOK + tid) << 6);
#pragma unroll
        for (int j4 = 0; j4 < 12; ++j4) {
            const float4 c4 = ((const float4*)crow)[j4];
            p[j4*4+0] = c4.x; p[j4*4+1] = c4.y; p[j4*4+2] = c4.z; p[j4*4+3] = c4.w;
        }
        p[48] = crow[48];

        // q row in packed-f32x2 registers
        unsigned long long q2[16];
        const ulonglong2* qp = (const ulonglong2*)(g_q + bh * (NTOK * HD) + tid * HD);
#pragma unroll
        for (int i = 0; i < 8; ++i) {
            const ulonglong2 t = qp[i];
            q2[2*i] = t.x; q2[2*i+1] = t.y;
        }

        float mx = -1e30f;
#pragma unroll
        for (int j = 0; j < NTOK; ++j) {
            const ulonglong2* kr = (const ulonglong2*)(sk + j * 32);
            unsigned long long a0 = 0ull, a1 = 0ull;
#pragma unroll
            for (int i = 0; i < 8; ++i) {
                const ulonglong2 kk = kr[i];
                fma2(a0, q2[2*i],   kk.x);
                fma2(a1, q2[2*i+1], kk.y);
            }
            const float2 f0 = upk2(a0);
            const float2 f1 = upk2(a1);
            const float s = (f0.x + f0.y) + (f1.x + f1.y) + p[j];
            p[j] = s;
            mx = fmaxf(mx, s);
        }

        float sum = 0.f;
#pragma unroll
        for (int j = 0; j < NTOK; ++j) {
            const float e = __expf(p[j] - mx);
            p[j] = e;
            sum += e;
        }
        const float inv = 1.f / sum;

        unsigned long long acc2[16];
#pragma unroll
        for (int i = 0; i < 16; ++i) acc2[i] = 0ull;
#pragma unroll
        for (int j = 0; j < NTOK; ++j) {
            const unsigned long long w2 = pk2(p[j], p[j]);
            const ulonglong2* vr = (const ulonglong2*)(sv + j * 32);
#pragma unroll
            for (int i = 0; i < 8; ++i) {
                const ulonglong2 vv = vr[i];
                fma2(acc2[2*i],   w2, vv.x);
                fma2(acc2[2*i+1], w2, vv.y);
            }
        }

        float* op = g_att + (b * NTOK + tid) * EMB + h * HD;
#pragma unroll
        for (int i = 0; i < 8; ++i) {
            const float2 x = upk2(acc2[2*i]);
            const float2 y = upk2(acc2[2*i+1]);
            float4 o;
            o.x = x.x * inv; o.y = x.y * inv; o.z = y.x * inv; o.w = y.y * inv;
            ((float4*)op)[i] = o;
        }
    }
}

// ---------------------------------------------------------------------------
extern "C" void kernel_launch(void* const* d_in, const int* in_sizes, int n_in,
                              void* d_out, int out_size)
{
    const float* x          = (const float*)d_in[0];
    const float* mask       = (const float*)d_in[1];
    const float* qkv_w      = (const float*)d_in[2];
    const float* qkv_b      = (const float*)d_in[3];
    const float* proj_w     = (const float*)d_in[4];
    const float* proj_b     = (const float*)d_in[5];
    const float* bias_table = (const float*)d_in[6];
    float* out = (float*)d_out;

    cmb_kernel<<<64 * NHEADS, 256>>>(mask, bias_table);
    gemm_hmma<0><<<dim3(768 / 128, MROWS / 128), 128>>>(x, qkv_w, qkv_b, nullptr);
    attn_kernel<<<BQ * NHEADS, 64>>>();
    gemm_hmma<1><<<dim3(EMB / 128, MROWS / 128), 128>>>(nullptr, proj_w, proj_b, out);
}

// round 7
// speedup vs baseline: 1.1723x; 1.1723x over previous
#include <cuda_runtime.h>
#include <cuda_bf16.h>
#include <cstdint>

#define BQ 4096
#define NTOK 49
#define EMB 256
#define NHEADS 8
#define HD 32
#define MROWS (BQ*NTOK)   // 200704 = 128*1568
#define SPAD 40           // bf16 row stride (32 data + 8 pad): conflict-free ldmatrix

// Scratch (device globals: allocation-free), 16B aligned for float4 access
__device__ __align__(16) float g_q[BQ*NHEADS*NTOK*HD];
__device__ __align__(16) float g_k[BQ*NHEADS*NTOK*HD];
__device__ __align__(16) float g_v[BQ*NHEADS*NTOK*HD];
__device__ __align__(16) float g_att[MROWS*EMB];
__device__ __align__(16) float g_cmb[64*NHEADS*NTOK*64];  // mask+bias, j padded to 64

// ---------------------------------------------------------------------------
// PTX helpers
// ---------------------------------------------------------------------------
__device__ __forceinline__ uint32_t smem_u32(const void* p) {
    uint32_t a;
    asm("{ .reg .u64 t; cvta.to.shared.u64 t, %1; cvt.u32.u64 %0, t; }"
        : "=r"(a) : "l"(p));
    return a;
}

__device__ __forceinline__ void ldm_x4(uint32_t& r0, uint32_t& r1,
                                       uint32_t& r2, uint32_t& r3, uint32_t addr) {
    asm volatile("ldmatrix.sync.aligned.m8n8.x4.shared.b16 {%0,%1,%2,%3}, [%4];"
                 : "=r"(r0), "=r"(r1), "=r"(r2), "=r"(r3) : "r"(addr));
}

__device__ __forceinline__ void mma_bf16(float* c, uint32_t a0, uint32_t a1,
                                         uint32_t a2, uint32_t a3,
                                         uint32_t b0, uint32_t b1) {
    asm volatile(
        "mma.sync.aligned.m16n8k16.row.col.f32.bf16.bf16.f32 "
        "{%0,%1,%2,%3}, {%4,%5,%6,%7}, {%8,%9}, {%0,%1,%2,%3};"
        : "+f"(c[0]), "+f"(c[1]), "+f"(c[2]), "+f"(c[3])
        : "r"(a0), "r"(a1), "r"(a2), "r"(a3), "r"(b0), "r"(b1));
}

__device__ __forceinline__ uint32_t pack_bf2(float a, float b) {
    __nv_bfloat162 v = __floats2bfloat162_rn(a, b);
    return *reinterpret_cast<uint32_t*>(&v);
}

// packed f32x2 (Blackwell; PTX-only path, see SASS_QUICKREF FFMA2)
__device__ __forceinline__ unsigned long long pk2(float x, float y) {
    unsigned long long r;
    asm("mov.b64 %0, {%1, %2};" : "=l"(r) : "f"(x), "f"(y));
    return r;
}
__device__ __forceinline__ float2 upk2(unsigned long long v) {
    float2 f;
    asm("mov.b64 {%0, %1}, %2;" : "=f"(f.x), "=f"(f.y) : "l"(v));
    return f;
}
__device__ __forceinline__ void fma2(unsigned long long& d,
                                     unsigned long long a, unsigned long long b) {
    asm("fma.rn.f32x2 %0, %1, %2, %0;" : "+l"(d) : "l"(a), "l"(b));
}

// ---------------------------------------------------------------------------
// HMMA GEMM (R5 config): 128x128 CTA tile, 8 warps (2x4, 64x32 warp tiles),
// K in 8 chunks of 32, bf16 hi/lo split (3 passes), 2 CTAs/SM.
// MODE 0: A=x, W=qkv_w, scatter q/k/v (q scaled).  MODE 1: A=g_att, W=proj_w.
// ---------------------------------------------------------------------------
template<int MODE>
__global__ void __launch_bounds__(256, 2)
gemm_hmma(const float* __restrict__ A_in, const float* __restrict__ W,
          const float* __restrict__ bias, float* __restrict__ out)
{
    __shared__ __align__(16) __nv_bfloat16 s_ahi[128 * SPAD];
    __shared__ __align__(16) __nv_bfloat16 s_alo[128 * SPAD];
    __shared__ __align__(16) __nv_bfloat16 s_bhi[128 * SPAD];
    __shared__ __align__(16) __nv_bfloat16 s_blo[128 * SPAD];

    const float* __restrict__ A = (MODE == 0) ? A_in : (const float*)g_att;

    const int tid = threadIdx.x;
    const int wid = tid >> 5;
    const int lid = tid & 31;
    const int m0  = blockIdx.y * 128;
    const int n0b = blockIdx.x * 128;
    const int warpM = (wid >> 2) * 64;
    const int warpN = (wid & 3) * 32;

    const uint32_t uAhi = smem_u32(s_ahi);
    const uint32_t uAlo = smem_u32(s_alo);
    const uint32_t uBhi = smem_u32(s_bhi);
    const uint32_t uBlo = smem_u32(s_blo);

    // gmem load mapping: thread -> (row, 16 consecutive k)
    const int grow = tid >> 1;
    const int gkh  = (tid & 1) * 16;
    const float* Ag = A + (m0  + grow) * EMB + gkh;
    const float* Wg = W + (n0b + grow) * EMB + gkh;
    __nv_bfloat16* sa_h = s_ahi + grow * SPAD + gkh;
    __nv_bfloat16* sa_l = s_alo + grow * SPAD + gkh;
    __nv_bfloat16* sb_h = s_bhi + grow * SPAD + gkh;
    __nv_bfloat16* sb_l = s_blo + grow * SPAD + gkh;

    float acc[4][4][4];
#pragma unroll
    for (int i = 0; i < 4; i++)
#pragma unroll
        for (int j = 0; j < 4; j++)
#pragma unroll
            for (int r = 0; r < 4; r++) acc[i][j][r] = 0.f;

    const int aRow = warpM + (lid & 15);
    const int aCol = (lid >> 4) << 3;
    const int bRow = warpN + ((lid >> 4) << 3) + (lid & 7);
    const int bCol = ((lid >> 3) & 1) << 3;

    for (int c = 0; c < 8; ++c) {
        __syncthreads();   // protect smem from previous iteration's ldmatrix
        {
            const int ko = c * 32;
            float4 va0 = *(const float4*)(Ag + ko);
            float4 va1 = *(const float4*)(Ag + ko + 4);
            float4 va2 = *(const float4*)(Ag + ko + 8);
            float4 va3 = *(const float4*)(Ag + ko + 12);
            float4 vb0 = *(const float4*)(Wg + ko);
            float4 vb1 = *(const float4*)(Wg + ko + 4);
            float4 vb2 = *(const float4*)(Wg + ko + 8);
            float4 vb3 = *(const float4*)(Wg + ko + 12);

            float fa[16] = {va0.x,va0.y,va0.z,va0.w, va1.x,va1.y,va1.z,va1.w,
                            va2.x,va2.y,va2.z,va2.w, va3.x,va3.y,va3.z,va3.w};
            float fb[16] = {vb0.x,vb0.y,vb0.z,vb0.w, vb1.x,vb1.y,vb1.z,vb1.w,
                            vb2.x,vb2.y,vb2.z,vb2.w, vb3.x,vb3.y,vb3.z,vb3.w};

            uint32_t ah[8], al[8], bh[8], bl[8];
#pragma unroll
            for (int e = 0; e < 8; ++e) {
                const float x0 = fa[2*e], x1 = fa[2*e+1];
                ah[e] = pack_bf2(x0, x1);
                const __nv_bfloat162 hv = *reinterpret_cast<__nv_bfloat162*>(&ah[e]);
                al[e] = pack_bf2(x0 - __bfloat162float(hv.x),
                                 x1 - __bfloat162float(hv.y));

                const float y0 = fb[2*e], y1 = fb[2*e+1];
                bh[e] = pack_bf2(y0, y1);
                const __nv_bfloat162 bv = *reinterpret_cast<__nv_bfloat162*>(&bh[e]);
                bl[e] = pack_bf2(y0 - __bfloat162float(bv.x),
                                 y1 - __bfloat162float(bv.y));
            }
            ((uint4*)sa_h)[0] = make_uint4(ah[0],ah[1],ah[2],ah[3]);
            ((uint4*)sa_h)[1] = make_uint4(ah[4],ah[5],ah[6],ah[7]);
            ((uint4*)sa_l)[0] = make_uint4(al[0],al[1],al[2],al[3]);
            ((uint4*)sa_l)[1] = make_uint4(al[4],al[5],al[6],al[7]);
            ((uint4*)sb_h)[0] = make_uint4(bh[0],bh[1],bh[2],bh[3]);
            ((uint4*)sb_h)[1] = make_uint4(bh[4],bh[5],bh[6],bh[7]);
            ((uint4*)sb_l)[0] = make_uint4(bl[0],bl[1],bl[2],bl[3]);
            ((uint4*)sb_l)[1] = make_uint4(bl[4],bl[5],bl[6],bl[7]);
        }
        __syncthreads();

#pragma unroll
        for (int kk = 0; kk < 32; kk += 16) {
            uint32_t ahi[4][4], alo[4][4], bhi[4][2], blo[4][2];
#pragma unroll
            for (int i = 0; i < 4; ++i) {
                const uint32_t off = (uint32_t)(((aRow + i*16) * SPAD + kk + aCol) * 2);
                ldm_x4(ahi[i][0], ahi[i][1], ahi[i][2], ahi[i][3], uAhi + off);
                ldm_x4(alo[i][0], alo[i][1], alo[i][2], alo[i][3], uAlo + off);
            }
#pragma unroll
            for (int jj = 0; jj < 2; ++jj) {
                const uint32_t off = (uint32_t)(((bRow + jj*16) * SPAD + kk + bCol) * 2);
                uint32_t r0, r1, r2, r3;
                ldm_x4(r0, r1, r2, r3, uBhi + off);
                bhi[jj*2+0][0] = r0; bhi[jj*2+0][1] = r1;
                bhi[jj*2+1][0] = r2; bhi[jj*2+1][1] = r3;
                ldm_x4(r0, r1, r2, r3, uBlo + off);
                blo[jj*2+0][0] = r0; blo[jj*2+0][1] = r1;
                blo[jj*2+1][0] = r2; blo[jj*2+1][1] = r3;
            }
#pragma unroll
            for (int i = 0; i < 4; ++i)
#pragma unroll
                for (int j = 0; j < 4; ++j) {
                    mma_bf16(acc[i][j], ahi[i][0],ahi[i][1],ahi[i][2],ahi[i][3],
                             bhi[j][0], bhi[j][1]);
                    mma_bf16(acc[i][j], ahi[i][0],ahi[i][1],ahi[i][2],ahi[i][3],
                             blo[j][0], blo[j][1]);
                    mma_bf16(acc[i][j], alo[i][0],alo[i][1],alo[i][2],alo[i][3],
                             bhi[j][0], bhi[j][1]);
                }
        }
    }

    // ---- epilogue ----
#pragma unroll
    for (int i = 0; i < 4; ++i) {
#pragma unroll
        for (int j = 0; j < 4; ++j) {
            const int n = n0b + warpN + j * 8 + 2 * (lid & 3);
            const float b0 = bias[n], b1 = bias[n + 1];
#pragma unroll
            for (int half = 0; half < 2; ++half) {
                const int m = m0 + warpM + i * 16 + (lid >> 2) + half * 8;
                float2 o;
                o.x = acc[i][j][half*2+0] + b0;
                o.y = acc[i][j][half*2+1] + b1;
                if (MODE == 0) {
                    const int bb  = m / NTOK;
                    const int nn  = m - bb * NTOK;
                    const int sel = n >> 8;
                    const int h   = (n >> 5) & 7;
                    const int d   = n & 31;
                    if (sel == 0) { o.x *= 0.17677669529663687f; o.y *= 0.17677669529663687f; }
                    float* dst = (sel == 0 ? g_q : (sel == 1 ? g_k : g_v))
                                 + ((bb * NHEADS + h) * NTOK + nn) * HD + d;
                    *(float2*)dst = o;
                } else {
                    *(float2*)(out + m * EMB + n) = o;
                }
            }
        }
    }
}

// ---------------------------------------------------------------------------
// Precompute combined mask + relative-position bias: [64*8][49][64] (j padded)
// ---------------------------------------------------------------------------
__global__ void __launch_bounds__(256)
cmb_kernel(const float* __restrict__ mask, const float* __restrict__ bias_table)
{
    const int wh = blockIdx.x;           // 0..511 = w*8 + h
    const int w  = wh >> 3;
    const int h  = wh & 7;
    for (int e = threadIdx.x; e < NTOK * 64; e += 256) {
        const int q = e >> 6;
        const int j = e & 63;
        float v = 0.f;
        if (j < NTOK) {
            const int qi = q / 7, qj = q - (q / 7) * 7;
            const int ki = j / 7, kj = j - (j / 7) * 7;
            const int idx = (qi - ki + 6) * 13 + (qj - kj + 6);
            v = mask[(w * NTOK + q) * NTOK + j] + bias_table[idx * NHEADS + h];
        }
        g_cmb[(wh * NTOK + q) * 64 + j] = v;
    }
}

// ---------------------------------------------------------------------------
// Attention: one block per (b,h). Logits fully in registers (p[49]); combined
// mask+bias preloaded as logit init; f32x2 packed FMAs in QK and PV loops.
// ---------------------------------------------------------------------------
__global__ void __launch_bounds__(64)
attn_kernel()
{
    __shared__ __align__(16) float sk[NTOK * 32];
    __shared__ __align__(16) float sv[NTOK * 32];

    const int tid = threadIdx.x;
    const int bh  = blockIdx.x;
    const int b   = bh >> 3;
    const int h   = bh & 7;

    const float* kp = g_k + bh * (NTOK * HD);
    const float* vp = g_v + bh * (NTOK * HD);
    for (int i = tid; i < (NTOK * HD) / 4; i += 64) {
        ((float4*)sk)[i] = ((const float4*)kp)[i];
        ((float4*)sv)[i] = ((const float4*)vp)[i];
    }
    __syncthreads();

    if (tid < NTOK) {
        // logits init = combined mask + bias row
        float p[NTOK];
        const float* crow = g_cmb + ((((b & 63) * NHEADS + h) * NTOK + tid) << 6);
#pragma unroll
        for (int j4 = 0; j4 < 12; ++j4) {
            const float4 c4 = ((const float4*)crow)[j4];
            p[j4*4+0] = c4.x; p[j4*4+1] = c4.y; p[j4*4+2] = c4.z; p[j4*4+3] = c4.w;
        }
        p[48] = crow[48];

        // q row in packed-f32x2 registers
        unsigned long long q2[16];
        const ulonglong2* qp = (const ulonglong2*)(g_q + bh * (NTOK * HD) + tid * HD);
#pragma unroll
        for (int i = 0; i < 8; ++i) {
            const ulonglong2 t = qp[i];
            q2[2*i] = t.x; q2[2*i+1] = t.y;
        }

        float mx = -1e30f;
#pragma unroll
        for (int j = 0; j < NTOK; ++j) {
            const ulonglong2* kr = (const ulonglong2*)(sk + j * 32);
            unsigned long long a0 = 0ull, a1 = 0ull;
#pragma unroll
            for (int i = 0; i < 8; ++i) {
                const ulonglong2 kk = kr[i];
                fma2(a0, q2[2*i],   kk.x);
                fma2(a1, q2[2*i+1], kk.y);
            }
            const float2 f0 = upk2(a0);
            const float2 f1 = upk2(a1);
            const float s = (f0.x + f0.y) + (f1.x + f1.y) + p[j];
            p[j] = s;
            mx = fmaxf(mx, s);
        }

        float sum = 0.f;
#pragma unroll
        for (int j = 0; j < NTOK; ++j) {
            const float e = __expf(p[j] - mx);
            p[j] = e;
            sum += e;
        }
        const float inv = 1.f / sum;

        unsigned long long acc2[16];
#pragma unroll
        for (int i = 0; i < 16; ++i) acc2[i] = 0ull;
#pragma unroll
        for (int j = 0; j < NTOK; ++j) {
            const unsigned long long w2 = pk2(p[j], p[j]);
            const ulonglong2* vr = (const ulonglong2*)(sv + j * 32);
#pragma unroll
            for (int i = 0; i < 8; ++i) {
                const ulonglong2 vv = vr[i];
                fma2(acc2[2*i],   w2, vv.x);
                fma2(acc2[2*i+1], w2, vv.y);
            }
        }

        float* op = g_att + (b * NTOK + tid) * EMB + h * HD;
#pragma unroll
        for (int i = 0; i < 8; ++i) {
            const float2 x = upk2(acc2[2*i]);
            const float2 y = upk2(acc2[2*i+1]);
            float4 o;
            o.x = x.x * inv; o.y = x.y * inv; o.z = y.x * inv; o.w = y.y * inv;
            ((float4*)op)[i] = o;
        }
    }
}

// ---------------------------------------------------------------------------
extern "C" void kernel_launch(void* const* d_in, const int* in_sizes, int n_in,
                              void* d_out, int out_size)
{
    const float* x          = (const float*)d_in[0];
    const float* mask       = (const float*)d_in[1];
    const float* qkv_w      = (const float*)d_in[2];
    const float* qkv_b      = (const float*)d_in[3];
    const float* proj_w     = (const float*)d_in[4];
    const float* proj_b     = (const float*)d_in[5];
    const float* bias_table = (const float*)d_in[6];
    float* out = (float*)d_out;

    cmb_kernel<<<64 * NHEADS, 256>>>(mask, bias_table);
    gemm_hmma<0><<<dim3(768 / 128, MROWS / 128), 256>>>(x, qkv_w, qkv_b, nullptr);
    attn_kernel<<<BQ * NHEADS, 64>>>();
    gemm_hmma<1><<<dim3(EMB / 128, MROWS / 128), 256>>>(nullptr, proj_w, proj_b, out);
}